// round 1
// baseline (speedup 1.0000x reference)
#include <cuda_runtime.h>

#define B_TOT 4096
#define T_ENC 168
#define T_DEC 24
#define NF    32
#define NT    8
#define HID   64
#define NG    256   // 4*HID

// Phase-1 scratch: XG0[b][t][g] = x[b,t,:] @ Wih0^T + bih0 + bhh0  (704 MB)
__device__ float g_xg0[(size_t)B_TOT * T_ENC * NG];

// ---------------------------------------------------------------------------
// activations (fast, ~1e-6 rel err — well inside the 1e-3 budget)
// ---------------------------------------------------------------------------
__device__ __forceinline__ float fsig(float x) {
    return __fdividef(1.f, 1.f + __expf(-x));
}
__device__ __forceinline__ float ftanh(float x) {
    float a = fabsf(x);
    float e = __expf(-2.f * a);
    float t = __fdividef(1.f - e, 1.f + e);
    return copysignf(t, x);
}

// ---------------------------------------------------------------------------
// Phase 1: XG0 precompute. Block = 32 (b,t) pairs, 256 threads.
// Thread tile: 4 rows x (2 j x 4 gate-blocks). W in smem k-major (padded 258).
// ---------------------------------------------------------------------------
__global__ void __launch_bounds__(256) xg0_kernel(
    const float* __restrict__ x, const float* __restrict__ Wih0,
    const float* __restrict__ bih0, const float* __restrict__ bhh0)
{
    __shared__ float xs[32 * NF];        // 4 KB, r-major
    __shared__ float ws[NF * 258];       // 33 KB, k-major padded (STS conflict fix)

    const int tid = threadIdx.x;
    const int p0 = blockIdx.x * 32;

    for (int idx = tid; idx < NG * NF; idx += 256) {    // coalesced LDG
        int k = idx & 31, g = idx >> 5;                  // Wih0[g][k]
        ws[k * 258 + g] = Wih0[idx];
    }
    ((float4*)xs)[tid] = ((const float4*)(x + (size_t)p0 * NF))[tid];
    __syncthreads();

    const int rg = tid >> 5, jg = tid & 31;
    const int r0 = rg * 4, j0 = jg * 2;

    float acc[4][4][2];
#pragma unroll
    for (int blk = 0; blk < 4; blk++)
#pragma unroll
        for (int jj = 0; jj < 2; jj++) {
            int g = blk * 64 + j0 + jj;
            float b = bih0[g] + bhh0[g];
#pragma unroll
            for (int rr = 0; rr < 4; rr++) acc[rr][blk][jj] = b;
        }

    for (int k = 0; k < NF; k += 4) {
        float4 hv[4];
#pragma unroll
        for (int rr = 0; rr < 4; rr++)
            hv[rr] = *(const float4*)&xs[(r0 + rr) * NF + k];
#pragma unroll
        for (int kk = 0; kk < 4; kk++) {
#pragma unroll
            for (int blk = 0; blk < 4; blk++) {
                float2 w = *(const float2*)&ws[(k + kk) * 258 + blk * 64 + j0];
#pragma unroll
                for (int rr = 0; rr < 4; rr++) {
                    float h = kk == 0 ? hv[rr].x : kk == 1 ? hv[rr].y
                             : kk == 2 ? hv[rr].z : hv[rr].w;
                    acc[rr][blk][0] = fmaf(h, w.x, acc[rr][blk][0]);
                    acc[rr][blk][1] = fmaf(h, w.y, acc[rr][blk][1]);
                }
            }
        }
    }

#pragma unroll
    for (int rr = 0; rr < 4; rr++) {
        float* dst = g_xg0 + (size_t)(p0 + r0 + rr) * NG;
#pragma unroll
        for (int blk = 0; blk < 4; blk++)
            *(float2*)&dst[blk * 64 + j0] =
                make_float2(acc[rr][blk][0], acc[rr][blk][1]);
    }
}

// ---------------------------------------------------------------------------
// Phase 2 helpers
// ---------------------------------------------------------------------------
// acc[r][blk][jj] += hbuf[r0+r][k] * wrows[k][blk*64 + j0 + jj],  k in [0,K)
__device__ __forceinline__ void gemm_acc(
    float acc[4][4][2], const float* __restrict__ hbuf, int hstride,
    const float* __restrict__ wrows, int K, int r0, int j0)
{
    for (int k = 0; k < K; k += 4) {
        float4 hv[4];
#pragma unroll
        for (int rr = 0; rr < 4; rr++)
            hv[rr] = *(const float4*)&hbuf[(r0 + rr) * hstride + k];
#pragma unroll
        for (int kk = 0; kk < 4; kk++) {
#pragma unroll
            for (int blk = 0; blk < 4; blk++) {
                float2 w = *(const float2*)&wrows[(k + kk) * NG + blk * 64 + j0];
#pragma unroll
                for (int rr = 0; rr < 4; rr++) {
                    float h = kk == 0 ? hv[rr].x : kk == 1 ? hv[rr].y
                             : kk == 2 ? hv[rr].z : hv[rr].w;
                    acc[rr][blk][0] = fmaf(h, w.x, acc[rr][blk][0]);
                    acc[rr][blk][1] = fmaf(h, w.y, acc[rr][blk][1]);
                }
            }
        }
    }
}

__device__ __forceinline__ void acc_init_bias(
    float acc[4][4][2], const float* __restrict__ bs, int j0)
{
#pragma unroll
    for (int blk = 0; blk < 4; blk++) {
        float2 b = *(const float2*)&bs[blk * 64 + j0];
#pragma unroll
        for (int rr = 0; rr < 4; rr++) {
            acc[rr][blk][0] = b.x;
            acc[rr][blk][1] = b.y;
        }
    }
}

// PyTorch gate order: blk0=i, blk1=f, blk2=g, blk3=o
__device__ __forceinline__ void cell_update(
    float acc[4][4][2], float c[4][2], float hn[4][2])
{
#pragma unroll
    for (int rr = 0; rr < 4; rr++)
#pragma unroll
        for (int jj = 0; jj < 2; jj++) {
            float ig = fsig(acc[rr][0][jj]);
            float fg = fsig(acc[rr][1][jj]);
            float gg = ftanh(acc[rr][2][jj]);
            float og = fsig(acc[rr][3][jj]);
            float cn = fmaf(fg, c[rr][jj], ig * gg);
            c[rr][jj] = cn;
            hn[rr][jj] = og * ftanh(cn);
        }
}

__device__ __forceinline__ void h_store(
    const float hn[4][2], float* __restrict__ hbuf, int r0, int j0)
{
#pragma unroll
    for (int rr = 0; rr < 4; rr++)
        *(float2*)&hbuf[(r0 + rr) * HID + j0] = make_float2(hn[rr][0], hn[rr][1]);
}

// smem layout (floats)
#define SM_W0    0                       // 72*256  (enc uses first 64 rows)
#define SM_W1    (SM_W0 + 72 * NG)       // 128*256
#define SM_B0    (SM_W1 + 128 * NG)      // 256
#define SM_B1    (SM_B0 + NG)            // 256
#define SM_FCW   (SM_B1 + NG)            // 512
#define SM_FCB   (SM_FCW + HID * NT)     // 16 (8 used)
#define SM_H0    (SM_FCB + 16)           // 32*64
#define SM_H1    (SM_H0 + 32 * HID)      // 32*64
#define SM_DIN   (SM_H1 + 32 * HID)      // 32*8
#define SM_TOTAL (SM_DIN + 32 * NT)      // 56592 floats = 226368 B
#define SMEM_BYTES (SM_TOTAL * 4)

// ---------------------------------------------------------------------------
// Phase 2: persistent recurrent kernel. 128 blocks x 256 threads, 32 rows each.
// ---------------------------------------------------------------------------
__global__ void __launch_bounds__(256, 1) seq2seq_kernel(
    const float* __restrict__ eWhh0,
    const float* __restrict__ eWih1, const float* __restrict__ eWhh1,
    const float* __restrict__ ebih1, const float* __restrict__ ebhh1,
    const float* __restrict__ dWih0, const float* __restrict__ dWhh0,
    const float* __restrict__ dbih0, const float* __restrict__ dbhh0,
    const float* __restrict__ dWih1, const float* __restrict__ dWhh1,
    const float* __restrict__ dbih1, const float* __restrict__ dbhh1,
    const float* __restrict__ fcW, const float* __restrict__ fcBias,
    float* __restrict__ out)
{
    extern __shared__ float sm[];
    float* w0s = sm + SM_W0;
    float* w1s = sm + SM_W1;
    float* b0s = sm + SM_B0;
    float* b1s = sm + SM_B1;
    float* fcw = sm + SM_FCW;
    float* fcb = sm + SM_FCB;
    float* h0s = sm + SM_H0;
    float* h1s = sm + SM_H1;
    float* din = sm + SM_DIN;

    const int tid = threadIdx.x;
    const int b0 = blockIdx.x * 32;
    const int rg = tid >> 5, jg = tid & 31;
    const int r0 = rg * 4, j0 = jg * 2;

    // ---- load encoder weights, k-major ----
    for (int idx = tid; idx < HID * NG; idx += 256) {
        int k = idx >> 8, g = idx & 255;
        w0s[idx] = eWhh0[g * HID + k];
        w1s[idx] = eWih1[g * HID + k];
        w1s[HID * NG + idx] = eWhh1[g * HID + k];
    }
    if (tid < NG) b1s[tid] = ebih1[tid] + ebhh1[tid];
    for (int idx = tid; idx < 32 * HID; idx += 256) { h0s[idx] = 0.f; h1s[idx] = 0.f; }
    __syncthreads();

    float c0[4][2] = {{0,0},{0,0},{0,0},{0,0}};
    float c1[4][2] = {{0,0},{0,0},{0,0},{0,0}};
    float acc[4][4][2];
    float hn[4][2];

    // ================= encoder =================
    for (int t = 0; t < T_ENC; t++) {
        // layer 0: acc = XG0[.,t,.] + h0 @ Whh0^T
#pragma unroll
        for (int rr = 0; rr < 4; rr++) {
            const float* src = g_xg0 + ((size_t)(b0 + r0 + rr) * T_ENC + t) * NG;
#pragma unroll
            for (int blk = 0; blk < 4; blk++) {
                float2 v = *(const float2*)&src[blk * 64 + j0];
                acc[rr][blk][0] = v.x;
                acc[rr][blk][1] = v.y;
            }
        }
        gemm_acc(acc, h0s, HID, w0s, HID, r0, j0);
        cell_update(acc, c0, hn);
        __syncthreads();                 // everyone done reading old h0
        h_store(hn, h0s, r0, j0);
        __syncthreads();

        // layer 1: acc = b1 + h0_new @ Wih1^T + h1 @ Whh1^T
        acc_init_bias(acc, b1s, j0);
        gemm_acc(acc, h0s, HID, w1s, HID, r0, j0);
        gemm_acc(acc, h1s, HID, w1s + HID * NG, HID, r0, j0);
        cell_update(acc, c1, hn);
        __syncthreads();
        h_store(hn, h1s, r0, j0);
        __syncthreads();
    }

    // ---- swap in decoder weights (all readers are past the barrier) ----
    for (int idx = tid; idx < NT * NG; idx += 256) {     // dec_Wih0 -> rows 0..7
        int k = idx >> 8, g = idx & 255;
        w0s[idx] = dWih0[g * NT + k];
    }
    for (int idx = tid; idx < HID * NG; idx += 256) {
        int k = idx >> 8, g = idx & 255;
        w0s[NT * NG + idx] = dWhh0[g * HID + k];          // rows 8..71
        w1s[idx] = dWih1[g * HID + k];
        w1s[HID * NG + idx] = dWhh1[g * HID + k];
    }
    if (tid < NG) {
        b0s[tid] = dbih0[tid] + dbhh0[tid];
        b1s[tid] = dbih1[tid] + dbhh1[tid];
    }
    for (int idx = tid; idx < HID * NT; idx += 256) {     // fc_W[o][j] -> fcw[j][o]
        int j = idx >> 3, o = idx & 7;
        fcw[idx] = fcW[o * HID + j];
    }
    if (tid < NT) fcb[tid] = fcBias[tid];
    for (int idx = tid; idx < 32 * NT; idx += 256) din[idx] = 0.f;
    __syncthreads();

    // ================= decoder =================
    for (int s = 0; s < T_DEC; s++) {
        // layer 0: [din(8); h0(64)] @ [Wih0; Whh0]
        acc_init_bias(acc, b0s, j0);
        gemm_acc(acc, din, NT, w0s, NT, r0, j0);
        gemm_acc(acc, h0s, HID, w0s + NT * NG, HID, r0, j0);
        cell_update(acc, c0, hn);
        __syncthreads();
        h_store(hn, h0s, r0, j0);
        __syncthreads();

        // layer 1
        acc_init_bias(acc, b1s, j0);
        gemm_acc(acc, h0s, HID, w1s, HID, r0, j0);
        gemm_acc(acc, h1s, HID, w1s + HID * NG, HID, r0, j0);
        cell_update(acc, c1, hn);
        __syncthreads();
        h_store(hn, h1s, r0, j0);
        __syncthreads();

        // FC: one (row, out) per thread
        {
            int r = tid >> 3, o = tid & 7;
            float a = fcb[o];
#pragma unroll 8
            for (int j = 0; j < HID; j++)
                a = fmaf(h1s[r * HID + j], fcw[j * NT + o], a);
            out[((size_t)(b0 + r) * T_DEC + s) * NT + o] = a;
            din[r * NT + o] = a;
        }
        __syncthreads();   // din visible before next step's layer-0 reads
    }
}

// ---------------------------------------------------------------------------
extern "C" void kernel_launch(void* const* d_in, const int* in_sizes, int n_in,
                              void* d_out, int out_size)
{
    const float* x     = (const float*)d_in[0];
    const float* eWih0 = (const float*)d_in[1];
    const float* eWhh0 = (const float*)d_in[2];
    const float* ebih0 = (const float*)d_in[3];
    const float* ebhh0 = (const float*)d_in[4];
    const float* eWih1 = (const float*)d_in[5];
    const float* eWhh1 = (const float*)d_in[6];
    const float* ebih1 = (const float*)d_in[7];
    const float* ebhh1 = (const float*)d_in[8];
    const float* dWih0 = (const float*)d_in[9];
    const float* dWhh0 = (const float*)d_in[10];
    const float* dbih0 = (const float*)d_in[11];
    const float* dbhh0 = (const float*)d_in[12];
    const float* dWih1 = (const float*)d_in[13];
    const float* dWhh1 = (const float*)d_in[14];
    const float* dbih1 = (const float*)d_in[15];
    const float* dbhh1 = (const float*)d_in[16];
    const float* fcW   = (const float*)d_in[17];
    const float* fcb   = (const float*)d_in[18];
    float* out = (float*)d_out;

    cudaFuncSetAttribute(seq2seq_kernel,
                         cudaFuncAttributeMaxDynamicSharedMemorySize, SMEM_BYTES);

    xg0_kernel<<<(B_TOT * T_ENC) / 32, 256>>>(x, eWih0, ebih0, ebhh0);
    seq2seq_kernel<<<B_TOT / 32, 256, SMEM_BYTES>>>(
        eWhh0, eWih1, eWhh1, ebih1, ebhh1,
        dWih0, dWhh0, dbih0, dbhh0, dWih1, dWhh1, dbih1, dbhh1,
        fcW, fcb, out);
}

// round 2
// speedup vs baseline: 1.0883x; 1.0883x over previous
#include <cuda_runtime.h>

#define B_TOT 4096
#define T_ENC 168
#define T_DEC 24
#define NF    32
#define NT    8
#define HID   64
#define NG    256   // 4*HID

// Phase-1 scratch: XG0[b][t][g] = x[b,t,:] @ Wih0^T + bih0 + bhh0  (704 MB)
__device__ float g_xg0[(size_t)B_TOT * T_ENC * NG];

// ---------------------------------------------------------------------------
// packed fp32 helpers (fma.rn.f32x2 — 2x FFMA rate; ptxas never emits this)
// ---------------------------------------------------------------------------
typedef unsigned long long u64;

__device__ __forceinline__ u64 pack2(float v) {
    u64 r;
    unsigned int b = __float_as_uint(v);
    asm("mov.b64 %0, {%1, %2};" : "=l"(r) : "r"(b), "r"(b));
    return r;
}
__device__ __forceinline__ void fma2(u64& acc, u64 a, u64 b) {
    asm("fma.rn.f32x2 %0, %1, %2, %0;" : "+l"(acc) : "l"(a), "l"(b));
}
__device__ __forceinline__ float2 unpack2(u64 v) {
    unsigned int lo, hi;
    asm("mov.b64 {%0, %1}, %2;" : "=r"(lo), "=r"(hi) : "l"(v));
    return make_float2(__uint_as_float(lo), __uint_as_float(hi));
}

// activations
__device__ __forceinline__ float fsig(float x) {
    return __fdividef(1.f, 1.f + __expf(-x));
}
__device__ __forceinline__ float ftanh(float x) {
    float a = fabsf(x);
    float e = __expf(-2.f * a);
    float t = __fdividef(1.f - e, 1.f + e);
    return copysignf(t, x);
}

// ---------------------------------------------------------------------------
// Core GEMM tile: acc[rr][blk] (f32x2 pairs) += hT[k][r0+rr] * ws[k][col..]
//   hT : transposed activations [K][hstride rows], float4 loads conflict-free
//   ws : weights k-major [K][wstride], u64 loads 4-way broadcast per warp
//   col = blk*64 + jcol, jcol = warp*8 + (lane&3)*2
// ---------------------------------------------------------------------------
__device__ __forceinline__ void gemm2(
    u64 acc[4][4], const float* __restrict__ hT, int hstride,
    const float* __restrict__ ws, int wstride, int K, int r0, int jcol)
{
#pragma unroll 2
    for (int k = 0; k < K; k += 4) {
#pragma unroll
        for (int kk = 0; kk < 4; kk++) {
            float4 a = *(const float4*)&hT[(k + kk) * hstride + r0];
            const float* wr = ws + (k + kk) * wstride + jcol;
            u64 w0 = *(const u64*)(wr);
            u64 w1 = *(const u64*)(wr + 64);
            u64 w2 = *(const u64*)(wr + 128);
            u64 w3 = *(const u64*)(wr + 192);
            u64 h0 = pack2(a.x), h1 = pack2(a.y), h2 = pack2(a.z), h3 = pack2(a.w);
            fma2(acc[0][0], h0, w0); fma2(acc[0][1], h0, w1);
            fma2(acc[0][2], h0, w2); fma2(acc[0][3], h0, w3);
            fma2(acc[1][0], h1, w0); fma2(acc[1][1], h1, w1);
            fma2(acc[1][2], h1, w2); fma2(acc[1][3], h1, w3);
            fma2(acc[2][0], h2, w0); fma2(acc[2][1], h2, w1);
            fma2(acc[2][2], h2, w2); fma2(acc[2][3], h2, w3);
            fma2(acc[3][0], h3, w0); fma2(acc[3][1], h3, w1);
            fma2(acc[3][2], h3, w2); fma2(acc[3][3], h3, w3);
        }
    }
}

// PyTorch gate order: blk0=i, blk1=f, blk2=g, blk3=o
__device__ __forceinline__ void cell_update(
    const u64 acc[4][4], float c[4][2], float hn[4][2])
{
#pragma unroll
    for (int rr = 0; rr < 4; rr++) {
        float2 gi = unpack2(acc[rr][0]);
        float2 gf = unpack2(acc[rr][1]);
        float2 gg = unpack2(acc[rr][2]);
        float2 go = unpack2(acc[rr][3]);
        float cn0 = fmaf(fsig(gf.x), c[rr][0], fsig(gi.x) * ftanh(gg.x));
        float cn1 = fmaf(fsig(gf.y), c[rr][1], fsig(gi.y) * ftanh(gg.y));
        c[rr][0] = cn0; c[rr][1] = cn1;
        hn[rr][0] = fsig(go.x) * ftanh(cn0);
        hn[rr][1] = fsig(go.y) * ftanh(cn1);
    }
}

// store hn (4 rows x 2 j) into transposed hT[j][row] (stride 32)
__device__ __forceinline__ void h_store(
    const float hn[4][2], float* __restrict__ hT, int r0, int jcol)
{
    *(float4*)&hT[(jcol + 0) * 32 + r0] =
        make_float4(hn[0][0], hn[1][0], hn[2][0], hn[3][0]);
    *(float4*)&hT[(jcol + 1) * 32 + r0] =
        make_float4(hn[0][1], hn[1][1], hn[2][1], hn[3][1]);
}

// ---------------------------------------------------------------------------
// Phase 1: XG0 precompute. Block = 32 (b,t) pairs, 256 threads.
// ---------------------------------------------------------------------------
#define XS_STRIDE 36
__global__ void __launch_bounds__(256) xg0_kernel(
    const float* __restrict__ x, const float* __restrict__ Wih0,
    const float* __restrict__ bih0, const float* __restrict__ bhh0)
{
    __shared__ float xs[NF * XS_STRIDE];   // transposed [k][row]
    __shared__ float ws[NF * 258];         // k-major padded
    __shared__ float bs[NG];

    const int tid = threadIdx.x;
    const int p0 = blockIdx.x * 32;

    for (int idx = tid; idx < NG * NF; idx += 256) {    // coalesced LDG
        int k = idx & 31, g = idx >> 5;                  // Wih0[g][k]
        ws[k * 258 + g] = Wih0[idx];
    }
    {
        int r = tid >> 5, k = tid & 31;                  // coalesced x read
        float4 v = ((const float4*)(x + (size_t)(p0 + r) * NF))[k & 7];
        // simpler: scalar transpose fill (one pass, 4 elems per thread)
        (void)v;
    }
    for (int idx = tid; idx < 32 * NF; idx += 256) {
        int r = idx >> 5, k = idx & 31;                  // read contiguous
        xs[k * XS_STRIDE + r] = x[(size_t)(p0 + r) * NF + k];
    }
    if (tid < NG) bs[tid] = bih0[tid] + bhh0[tid];
    __syncthreads();

    const int wid = tid >> 5, lane = tid & 31;
    const int r0 = (lane >> 2) * 4;
    const int jcol = wid * 8 + (lane & 3) * 2;

    u64 acc[4][4];
#pragma unroll
    for (int blk = 0; blk < 4; blk++) {
        u64 b = *(const u64*)&bs[blk * 64 + jcol];
#pragma unroll
        for (int rr = 0; rr < 4; rr++) acc[rr][blk] = b;
    }

    gemm2(acc, xs, XS_STRIDE, ws, 258, NF, r0, jcol);

#pragma unroll
    for (int rr = 0; rr < 4; rr++) {
        float* dst = g_xg0 + (size_t)(p0 + r0 + rr) * NG + jcol;
#pragma unroll
        for (int blk = 0; blk < 4; blk++)
            *(u64*)(dst + blk * 64) = acc[rr][blk];
    }
}

// ---------------------------------------------------------------------------
// Phase 2 smem layout (floats). dinT | hT0 | hT1 contiguous, all stride 32,
// so decoder-L0 (K=72), enc/dec-L1 (K=128) are single contiguous-K GEMMs.
// ---------------------------------------------------------------------------
#define SM_W0    0                       // 72*256  (enc uses first 64 rows)
#define SM_W1    (SM_W0 + 72 * NG)       // 128*256
#define SM_B0    (SM_W1 + 128 * NG)
#define SM_B1    (SM_B0 + NG)
#define SM_FCW   (SM_B1 + NG)            // 512
#define SM_FCB   (SM_FCW + HID * NT)     // 16
#define SM_DIN   (SM_FCB + 16)           // 8*32  (transposed)
#define SM_H0    (SM_DIN + NT * 32)      // 64*32 (transposed)
#define SM_H1    (SM_H0 + HID * 32)      // 64*32 (transposed)
#define SM_TOTAL (SM_H1 + HID * 32)
#define SMEM_BYTES (SM_TOTAL * 4)

__global__ void __launch_bounds__(256, 1) seq2seq_kernel(
    const float* __restrict__ eWhh0,
    const float* __restrict__ eWih1, const float* __restrict__ eWhh1,
    const float* __restrict__ ebih1, const float* __restrict__ ebhh1,
    const float* __restrict__ dWih0, const float* __restrict__ dWhh0,
    const float* __restrict__ dbih0, const float* __restrict__ dbhh0,
    const float* __restrict__ dWih1, const float* __restrict__ dWhh1,
    const float* __restrict__ dbih1, const float* __restrict__ dbhh1,
    const float* __restrict__ fcW, const float* __restrict__ fcBias,
    float* __restrict__ out)
{
    extern __shared__ float sm[];
    float* w0s = sm + SM_W0;
    float* w1s = sm + SM_W1;
    float* b0s = sm + SM_B0;
    float* b1s = sm + SM_B1;
    float* fcw = sm + SM_FCW;
    float* fcb = sm + SM_FCB;
    float* dinT = sm + SM_DIN;
    float* h0T = sm + SM_H0;
    float* h1T = sm + SM_H1;

    const int tid = threadIdx.x;
    const int b0 = blockIdx.x * 32;
    const int wid = tid >> 5, lane = tid & 31;
    const int r0 = (lane >> 2) * 4;
    const int jcol = wid * 8 + (lane & 3) * 2;

    // ---- load encoder weights, k-major ----
    for (int idx = tid; idx < HID * NG; idx += 256) {
        int k = idx >> 8, g = idx & 255;
        w0s[idx] = eWhh0[g * HID + k];
        w1s[idx] = eWih1[g * HID + k];
        w1s[HID * NG + idx] = eWhh1[g * HID + k];
    }
    if (tid < NG) b1s[tid] = ebih1[tid] + ebhh1[tid];
    for (int idx = tid; idx < HID * 32; idx += 256) { h0T[idx] = 0.f; h1T[idx] = 0.f; }
    __syncthreads();

    float c0[4][2] = {{0,0},{0,0},{0,0},{0,0}};
    float c1[4][2] = {{0,0},{0,0},{0,0},{0,0}};
    u64 acc[4][4];
    float hn[4][2];

    // ================= encoder =================
    for (int t = 0; t < T_ENC; t++) {
        // layer 0: acc = XG0[.,t,.] + h0 @ Whh0^T
#pragma unroll
        for (int rr = 0; rr < 4; rr++) {
            const float* src =
                g_xg0 + ((size_t)(b0 + r0 + rr) * T_ENC + t) * NG + jcol;
#pragma unroll
            for (int blk = 0; blk < 4; blk++)
                acc[rr][blk] = *(const u64*)(src + blk * 64);
        }
        gemm2(acc, h0T, 32, w0s, NG, HID, r0, jcol);
        cell_update(acc, c0, hn);
        __syncthreads();                 // everyone done reading old h0
        h_store(hn, h0T, r0, jcol);
        __syncthreads();

        // layer 1: acc = b1 + [h0;h1] @ [Wih1;Whh1]^T   (K=128 contiguous)
#pragma unroll
        for (int blk = 0; blk < 4; blk++) {
            u64 b = *(const u64*)&b1s[blk * 64 + jcol];
#pragma unroll
            for (int rr = 0; rr < 4; rr++) acc[rr][blk] = b;
        }
        gemm2(acc, h0T, 32, w1s, NG, 2 * HID, r0, jcol);
        cell_update(acc, c1, hn);
        __syncthreads();
        h_store(hn, h1T, r0, jcol);
        __syncthreads();
    }

    // ---- swap in decoder weights ----
    for (int idx = tid; idx < NT * NG; idx += 256) {     // dec_Wih0 -> rows 0..7
        int k = idx >> 8, g = idx & 255;
        w0s[idx] = dWih0[g * NT + k];
    }
    for (int idx = tid; idx < HID * NG; idx += 256) {
        int k = idx >> 8, g = idx & 255;
        w0s[NT * NG + idx] = dWhh0[g * HID + k];          // rows 8..71
        w1s[idx] = dWih1[g * HID + k];
        w1s[HID * NG + idx] = dWhh1[g * HID + k];
    }
    if (tid < NG) {
        b0s[tid] = dbih0[tid] + dbhh0[tid];
        b1s[tid] = dbih1[tid] + dbhh1[tid];
    }
    for (int idx = tid; idx < HID * NT; idx += 256) {     // fc_W[o][j] -> fcw[j][o]
        int j = idx >> 3, o = idx & 7;
        fcw[idx] = fcW[o * HID + j];
    }
    if (tid < NT) fcb[tid] = fcBias[tid];
    for (int idx = tid; idx < NT * 32; idx += 256) dinT[idx] = 0.f;
    __syncthreads();

    // ================= decoder =================
    for (int s = 0; s < T_DEC; s++) {
        // layer 0: [din(8); h0(64)] @ [Wih0; Whh0]   (K=72 contiguous)
#pragma unroll
        for (int blk = 0; blk < 4; blk++) {
            u64 b = *(const u64*)&b0s[blk * 64 + jcol];
#pragma unroll
            for (int rr = 0; rr < 4; rr++) acc[rr][blk] = b;
        }
        gemm2(acc, dinT, 32, w0s, NG, NT + HID, r0, jcol);
        cell_update(acc, c0, hn);
        __syncthreads();
        h_store(hn, h0T, r0, jcol);
        __syncthreads();

        // layer 1: [h0;h1] @ [Wih1;Whh1]   (K=128 contiguous)
#pragma unroll
        for (int blk = 0; blk < 4; blk++) {
            u64 b = *(const u64*)&b1s[blk * 64 + jcol];
#pragma unroll
            for (int rr = 0; rr < 4; rr++) acc[rr][blk] = b;
        }
        gemm2(acc, h0T, 32, w1s, NG, 2 * HID, r0, jcol);
        cell_update(acc, c1, hn);
        __syncthreads();
        h_store(hn, h1T, r0, jcol);
        __syncthreads();

        // FC: one (row, out) per thread; h1T is transposed [j][row]
        {
            int r = tid >> 3, o = tid & 7;
            float a = fcb[o];
#pragma unroll 8
            for (int j = 0; j < HID; j++)
                a = fmaf(h1T[j * 32 + r], fcw[j * NT + o], a);
            out[((size_t)(b0 + r) * T_DEC + s) * NT + o] = a;
            dinT[o * 32 + r] = a;
        }
        __syncthreads();   // dinT visible before next step's layer-0 reads
    }
}

// ---------------------------------------------------------------------------
extern "C" void kernel_launch(void* const* d_in, const int* in_sizes, int n_in,
                              void* d_out, int out_size)
{
    const float* x     = (const float*)d_in[0];
    const float* eWih0 = (const float*)d_in[1];
    const float* eWhh0 = (const float*)d_in[2];
    const float* ebih0 = (const float*)d_in[3];
    const float* ebhh0 = (const float*)d_in[4];
    const float* eWih1 = (const float*)d_in[5];
    const float* eWhh1 = (const float*)d_in[6];
    const float* ebih1 = (const float*)d_in[7];
    const float* ebhh1 = (const float*)d_in[8];
    const float* dWih0 = (const float*)d_in[9];
    const float* dWhh0 = (const float*)d_in[10];
    const float* dbih0 = (const float*)d_in[11];
    const float* dbhh0 = (const float*)d_in[12];
    const float* dWih1 = (const float*)d_in[13];
    const float* dWhh1 = (const float*)d_in[14];
    const float* dbih1 = (const float*)d_in[15];
    const float* dbhh1 = (const float*)d_in[16];
    const float* fcW   = (const float*)d_in[17];
    const float* fcb   = (const float*)d_in[18];
    float* out = (float*)d_out;

    cudaFuncSetAttribute(seq2seq_kernel,
                         cudaFuncAttributeMaxDynamicSharedMemorySize, SMEM_BYTES);

    xg0_kernel<<<(B_TOT * T_ENC) / 32, 256>>>(x, eWih0, ebih0, ebhh0);
    seq2seq_kernel<<<B_TOT / 32, 256, SMEM_BYTES>>>(
        eWhh0, eWih1, eWhh1, ebih1, ebhh1,
        dWih0, dWhh0, dbih0, dbhh0, dWih1, dWhh1, dbih1, dbhh1,
        fcW, fcb, out);
}